// round 12
// baseline (speedup 1.0000x reference)
#include <cuda_runtime.h>
#include <cuda_fp16.h>
#include <math.h>

// Problem constants
#define BB 4
#define SS 2048
#define DD 1024
#define HH 16
#define DH 64
#define MM (BB * SS)   // 8192

#define MASKV  (-1e4f)
#define YCLAMP (-30.0f)

#define AP ((size_t)MM * DD)   // activation plane
#define WP ((size_t)DD * DD)   // weight plane

// ---------------------------------------------------------------------------
// Scratch (device globals)
// ---------------------------------------------------------------------------
__device__ __half g_ActHi[(size_t)3 * MM * DD];   // q/k/v splits; plane0 reused for ctx
__device__ __half g_ActLo[(size_t)3 * MM * DD];
__device__ __half g_WHi[(size_t)4 * DD * DD];     // wq, wk, wv, wo
__device__ __half g_WLo[(size_t)4 * DD * DD];

__device__ __half g_Qhi[(size_t)MM * DD];
__device__ __half g_Qlo[(size_t)MM * DD];
__device__ __half g_Khi[(size_t)MM * DD];
__device__ __half g_Klo[(size_t)MM * DD];
__device__ __half g_Vhi[(size_t)MM * DD];   // V^T layout: [b][h][dh][s]
__device__ __half g_Vlo[(size_t)MM * DD];

// ---------------------------------------------------------------------------
// mma.sync m16n8k16 f16 -> fp32 ; ldmatrix
// ---------------------------------------------------------------------------
__device__ __forceinline__ void mma16816h(float* c, const unsigned* a, const unsigned* b)
{
    asm volatile(
        "mma.sync.aligned.m16n8k16.row.col.f32.f16.f16.f32 "
        "{%0,%1,%2,%3}, {%4,%5,%6,%7}, {%8,%9}, {%0,%1,%2,%3};\n"
        : "+f"(c[0]), "+f"(c[1]), "+f"(c[2]), "+f"(c[3])
        : "r"(a[0]), "r"(a[1]), "r"(a[2]), "r"(a[3]), "r"(b[0]), "r"(b[1]));
}

__device__ __forceinline__ void ldsm4(unsigned& r0, unsigned& r1, unsigned& r2,
                                      unsigned& r3, unsigned addr)
{
    asm volatile("ldmatrix.sync.aligned.m8n8.x4.shared.b16 {%0,%1,%2,%3}, [%4];\n"
                 : "=r"(r0), "=r"(r1), "=r"(r2), "=r"(r3) : "r"(addr));
}

__device__ __forceinline__ void split2h(float x, float y, unsigned& hi, unsigned& lo)
{
    __half hx = __float2half(x);
    __half hy = __float2half(y);
    float rx = x - __half2float(hx);
    float ry = y - __half2float(hy);
    __half2 H(hx, hy);
    __half2 L(__float2half(rx), __float2half(ry));
    hi = *(unsigned*)&H;
    lo = *(unsigned*)&L;
}

// cp.async helpers
__device__ __forceinline__ void cp16(unsigned saddr, const void* g)
{
    asm volatile("cp.async.cg.shared.global [%0], [%1], 16;\n" :: "r"(saddr), "l"(g));
}
__device__ __forceinline__ void cp_commit()
{
    asm volatile("cp.async.commit_group;\n");
}
template<int N> __device__ __forceinline__ void cp_wait()
{
    asm volatile("cp.async.wait_group %0;\n" :: "n"(N));
}

// ---------------------------------------------------------------------------
// Batched splits
// ---------------------------------------------------------------------------
__device__ __forceinline__ void split_store(const float* X, __half* hi, __half* lo, int i)
{
    float4 x = ((const float4*)X)[i];
    unsigned h0, l0, h1, l1;
    split2h(x.x, x.y, h0, l0);
    split2h(x.z, x.w, h1, l1);
    unsigned* H = (unsigned*)(hi + (size_t)i * 4);
    unsigned* L = (unsigned*)(lo + (size_t)i * 4);
    H[0] = h0; H[1] = h1;
    L[0] = l0; L[1] = l1;
}

__global__ __launch_bounds__(256) void split_acts(
    const float* __restrict__ q, const float* __restrict__ k,
    const float* __restrict__ v, __half* __restrict__ hi, __half* __restrict__ lo)
{
    int i = blockIdx.x * blockDim.x + threadIdx.x;
    int n4 = (MM * DD) / 4;
    if (i >= n4) return;
    int z = blockIdx.y;
    const float* src = (z == 0) ? q : (z == 1) ? k : v;
    split_store(src, hi + (size_t)z * MM * DD, lo + (size_t)z * MM * DD, i);
}

__global__ __launch_bounds__(256) void split_wts(
    const float* __restrict__ w0, const float* __restrict__ w1,
    const float* __restrict__ w2, const float* __restrict__ w3,
    __half* __restrict__ hi, __half* __restrict__ lo)
{
    int i = blockIdx.x * blockDim.x + threadIdx.x;
    int n4 = (DD * DD) / 4;
    if (i >= n4) return;
    int z = blockIdx.y;
    const float* src = (z == 0) ? w0 : (z == 1) ? w1 : (z == 2) ? w2 : w3;
    split_store(src, hi + (size_t)z * DD * DD, lo + (size_t)z * DD * DD, i);
}

// ---------------------------------------------------------------------------
// Split-f16 tensor-core GEMM v5:
// BM=256, BN=128, BK=16, 512 threads, ldmatrix fragments,
// 4-stage cp.async pipeline with ONE __syncthreads per k-iteration.
// FUSED=1: grid.z = 3 (Q/K/V projections, per-z epilogue).
// FUSED=0: single GEMM, fp32 output (output projection).
// ---------------------------------------------------------------------------
#define GBM 256
#define GBN 128
#define GBUF 36864       // bytes per stage: A 2*12288 + W 2*6144
#define G_ALO 12288
#define G_WHI 24576
#define G_WLO 30720
#define G_SMEM (4 * GBUF)   // 147456

template<int FUSED>
__global__ __launch_bounds__(512) void gemm_v5(
    const __half* __restrict__ AhiB, const __half* __restrict__ AloB,
    const __half* __restrict__ WhiB, const __half* __restrict__ WloB,
    const float* __restrict__ bq, const float* __restrict__ bk,
    const float* __restrict__ bv, float qscale,
    float* __restrict__ Cf,
    __half* __restrict__ Qhi, __half* __restrict__ Qlo,
    __half* __restrict__ Khi, __half* __restrict__ Klo,
    __half* __restrict__ Vhi, __half* __restrict__ Vlo)
{
    extern __shared__ __align__(16) char gsm[];
    const unsigned sbase = (unsigned)__cvta_generic_to_shared(gsm);

    const int z    = FUSED ? blockIdx.z : 0;
    const __half* Ahi = AhiB + (FUSED ? (size_t)z * AP : 0);
    const __half* Alo = AloB + (FUSED ? (size_t)z * AP : 0);
    const __half* Whi = WhiB + (FUSED ? (size_t)z * WP : 0);
    const __half* Wlo = WloB + (FUSED ? (size_t)z * WP : 0);

    const int tid  = threadIdx.x;
    const int wid  = tid >> 5;
    const int lane = tid & 31;
    const int g    = lane >> 2;
    const int tig  = lane & 3;
    const int wr   = wid >> 2;    // 0..3 : 64-row group
    const int wc   = wid & 3;     // 0..3 : 32-col group
    const int m0   = blockIdx.y * GBM;
    const int n0   = blockIdx.x * GBN;

    float acc[4][4][4];
#pragma unroll
    for (int mt = 0; mt < 4; mt++)
#pragma unroll
        for (int nt = 0; nt < 4; nt++)
#pragma unroll
            for (int i = 0; i < 4; i++) acc[mt][nt][i] = 0.0f;

    // ldmatrix per-lane byte offsets (stride 48 B/row) — verified in R10
    unsigned aoff[4];
#pragma unroll
    for (int mt = 0; mt < 4; mt++)
        aoff[mt] = (unsigned)((wr * 64 + mt * 16 + (lane & 15)) * 48
                              + (lane >> 4) * 16);
    unsigned woff[2];
#pragma unroll
    for (int p = 0; p < 2; p++)
        woff[p] = (unsigned)((wc * 32 + p * 16 + ((lane >> 4) * 8) + (lane & 7)) * 48
                             + ((lane >> 3) & 1) * 16);

    const int ar = tid >> 1, ac = (tid & 1) * 8;
    auto fill = [&](int buf, int kt) {
        int k0 = kt * 16;
        unsigned sb = sbase + buf * GBUF;
        size_t aro = (size_t)(m0 + ar) * DD + k0 + ac;
        cp16(sb + ar * 48 + ac * 2,          Ahi + aro);
        cp16(sb + G_ALO + ar * 48 + ac * 2,  Alo + aro);
        if (tid < 256) {
            size_t wro = (size_t)(n0 + ar) * DD + k0 + ac;
            cp16(sb + G_WHI + ar * 48 + ac * 2, Whi + wro);
            cp16(sb + G_WLO + ar * 48 + ac * 2, Wlo + wro);
        }
    };

    fill(0, 0); cp_commit();
    fill(1, 1); cp_commit();
    fill(2, 2); cp_commit();

    for (int kt = 0; kt < 64; kt++) {
        cp_wait<2>();
        __syncthreads();
        // refill buffer consumed at kt-1 (safe: all warps passed the barrier)
        if (kt + 3 < 64) fill((kt + 3) & 3, kt + 3);
        cp_commit();

        unsigned sb = sbase + (kt & 3) * GBUF;

        unsigned af[4][4], bh[4][2], bl[4][2];
#pragma unroll
        for (int mt = 0; mt < 4; mt++)
            ldsm4(af[mt][0], af[mt][1], af[mt][2], af[mt][3], sb + aoff[mt]);
        ldsm4(bh[0][0], bh[0][1], bh[1][0], bh[1][1], sb + G_WHI + woff[0]);
        ldsm4(bh[2][0], bh[2][1], bh[3][0], bh[3][1], sb + G_WHI + woff[1]);
#pragma unroll
        for (int mt = 0; mt < 4; mt++)
#pragma unroll
            for (int nt = 0; nt < 4; nt++)
                mma16816h(acc[mt][nt], af[mt], bh[nt]);
        ldsm4(bl[0][0], bl[0][1], bl[1][0], bl[1][1], sb + G_WLO + woff[0]);
        ldsm4(bl[2][0], bl[2][1], bl[3][0], bl[3][1], sb + G_WLO + woff[1]);
#pragma unroll
        for (int mt = 0; mt < 4; mt++)
#pragma unroll
            for (int nt = 0; nt < 4; nt++)
                mma16816h(acc[mt][nt], af[mt], bl[nt]);
#pragma unroll
        for (int mt = 0; mt < 4; mt++)
            ldsm4(af[mt][0], af[mt][1], af[mt][2], af[mt][3], sb + G_ALO + aoff[mt]);
#pragma unroll
        for (int mt = 0; mt < 4; mt++)
#pragma unroll
            for (int nt = 0; nt < 4; nt++)
                mma16816h(acc[mt][nt], af[mt], bh[nt]);
    }

    // Epilogue
    const float* bias = FUSED ? ((z == 0) ? bq : (z == 1) ? bk : bv) : bq;
    const float scale = (FUSED && z == 0) ? qscale : 1.0f;

#pragma unroll
    for (int mt = 0; mt < 4; mt++) {
        int row = m0 + wr * 64 + mt * 16 + g;
#pragma unroll
        for (int nt = 0; nt < 4; nt++) {
            int col = n0 + wc * 32 + nt * 8 + 2 * tig;
            float b0 = bias[col], b1 = bias[col + 1];
            float v0 = (acc[mt][nt][0] + b0) * scale;
            float v1 = (acc[mt][nt][1] + b1) * scale;
            float v2 = (acc[mt][nt][2] + b0) * scale;
            float v3 = (acc[mt][nt][3] + b1) * scale;
            if (!FUSED) {
                *(float2*)&Cf[(size_t)row * DD + col] = make_float2(v0, v1);
                *(float2*)&Cf[(size_t)(row + 8) * DD + col] = make_float2(v2, v3);
            } else if (z < 2) {
                __half* Chi = (z == 0) ? Qhi : Khi;
                __half* Clo = (z == 0) ? Qlo : Klo;
                unsigned h01, l01, h23, l23;
                split2h(v0, v1, h01, l01);
                split2h(v2, v3, h23, l23);
                *(unsigned*)(Chi + (size_t)row * DD + col) = h01;
                *(unsigned*)(Clo + (size_t)row * DD + col) = l01;
                *(unsigned*)(Chi + (size_t)(row + 8) * DD + col) = h23;
                *(unsigned*)(Clo + (size_t)(row + 8) * DD + col) = l23;
            } else {
                // V^T: dst[((b*HH+h)*DH+dh)*SS + s]
                float vv[4] = {v0, v1, v2, v3};
                int rr[4] = {row, row, row + 8, row + 8};
                int cc[4] = {col, col + 1, col, col + 1};
#pragma unroll
                for (int e = 0; e < 4; e++) {
                    int bq_ = rr[e] >> 11, s = rr[e] & 2047;
                    int hh = cc[e] >> 6,  dh = cc[e] & 63;
                    size_t di = (((size_t)bq_ * HH + hh) * DH + dh) * SS + s;
                    __half hx = __float2half(vv[e]);
                    Vhi[di] = hx;
                    Vlo[di] = __float2half(vv[e] - __half2float(hx));
                }
            }
        }
    }
}

// ---------------------------------------------------------------------------
// Pipelined tensor-core causal flash attention (unchanged).
// ---------------------------------------------------------------------------
#define FA_SMEM 110592
#define STR 36

__global__ __launch_bounds__(256) void flash_attn_tc(
    const __half* __restrict__ Qhi_, const __half* __restrict__ Qlo_,
    const __half* __restrict__ Khi_, const __half* __restrict__ Klo_,
    const __half* __restrict__ VhiT_, const __half* __restrict__ VloT_,
    __half* __restrict__ CtxHi, __half* __restrict__ CtxLo)
{
    extern __shared__ __align__(16) char smraw[];
    const unsigned sbase = (unsigned)__cvta_generic_to_shared(smraw);

    const int tid  = threadIdx.x;
    const int w    = tid >> 5;
    const int lane = tid & 31;
    const int g    = lane >> 2;
    const int tig  = lane & 3;
    const int qt   = blockIdx.x;
    const int h    = blockIdx.y;
    const int b    = blockIdx.z;
    const int s0   = qt * 128;

    const size_t base   = ((size_t)b * SS) * DD + (size_t)h * DH;
    const size_t vtbase = ((size_t)(b * HH + h)) * DH * SS;

    const int wrow = s0 + w * 16;
    const int nkt  = 2 * (qt + 1);

    {
        int row = tid >> 1, hf = tid & 1;
        const __half* srcH = Qhi_ + base + (size_t)(s0 + row) * DD + hf * 32;
        const __half* srcL = Qlo_ + base + (size_t)(s0 + row) * DD + hf * 32;
        unsigned dH = sbase + (row * STR + hf * 16) * 4;
        unsigned dL = dH + 18432;
#pragma unroll
        for (int j = 0; j < 4; j++) {
            cp16(dH + j * 16, srcH + j * 8);
            cp16(dL + j * 16, srcL + j * 8);
        }
    }

    const int frow = tid >> 2;
    const int fc   = tid & 3;
    auto fillKV = [&](int buf, int c0) {
        size_t kro = base + (size_t)(c0 + frow) * DD;
        unsigned kH = sbase + 36864 + buf * 18432 + frow * 144;
        unsigned kL = kH + 9216;
        cp16(kH + fc * 16,       Khi_ + kro + fc * 8);
        cp16(kH + (fc + 4) * 16, Khi_ + kro + (fc + 4) * 8);
        cp16(kL + fc * 16,       Klo_ + kro + fc * 8);
        cp16(kL + (fc + 4) * 16, Klo_ + kro + (fc + 4) * 8);
        size_t vro = vtbase + (size_t)frow * SS + c0;
        unsigned vH = sbase + 73728 + buf * 18432 + frow * 144;
        unsigned vL = vH + 9216;
        cp16(vH + fc * 16,       VhiT_ + vro + fc * 8);
        cp16(vH + (fc + 4) * 16, VhiT_ + vro + (fc + 4) * 8);
        cp16(vL + fc * 16,       VloT_ + vro + fc * 8);
        cp16(vL + (fc + 4) * 16, VloT_ + vro + (fc + 4) * 8);
    };

    fillKV(0, 0);
    cp_commit();
    if (nkt > 1) fillKV(1, 64);
    cp_commit();

    float o[8][4];
    float mrun0 = MASKV, mrun1 = MASKV;
    float lrun0 = 0.0f,  lrun1 = 0.0f;
#pragma unroll
    for (int j = 0; j < 8; j++)
#pragma unroll
        for (int e = 0; e < 4; e++) o[j][e] = 0.0f;

    const unsigned* QHI = (const unsigned*)smraw;
    const unsigned* QLO = QHI + 4608;

    for (int kt = 0; kt < nkt; kt++) {
        const int c0 = kt * 64;
        if (kt + 1 < nkt) cp_wait<1>(); else cp_wait<0>();
        __syncthreads();

        const unsigned* KHI = (const unsigned*)(smraw + 36864 + (kt & 1) * 18432);
        const unsigned* KLO = KHI + 2304;
        const unsigned* VHI = (const unsigned*)(smraw + 73728 + (kt & 1) * 18432);
        const unsigned* VLO = VHI + 2304;

        if (c0 <= wrow + 15) {
            float p[8][4];
#pragma unroll
            for (int j = 0; j < 8; j++)
#pragma unroll
                for (int e = 0; e < 4; e++) p[j][e] = 0.0f;

#pragma unroll
            for (int kc = 0; kc < 4; kc++) {
                int abase = (w * 16 + g) * STR + kc * 8 + tig;
                unsigned ah[4], al[4];
                ah[0] = QHI[abase];           ah[1] = QHI[abase + 8 * STR];
                ah[2] = QHI[abase + 4];       ah[3] = QHI[abase + 8 * STR + 4];
                al[0] = QLO[abase];           al[1] = QLO[abase + 8 * STR];
                al[2] = QLO[abase + 4];       al[3] = QLO[abase + 8 * STR + 4];
#pragma unroll
                for (int j = 0; j < 8; j++) {
                    int bbase = (j * 8 + g) * STR + kc * 8 + tig;
                    unsigned bh[2] = {KHI[bbase], KHI[bbase + 4]};
                    unsigned bl[2] = {KLO[bbase], KLO[bbase + 4]};
                    mma16816h(p[j], ah, bh);
                    mma16816h(p[j], ah, bl);
                    mma16816h(p[j], al, bh);
                }
            }

            if (c0 + 63 > wrow) {
                int r0 = wrow + g, r1 = wrow + g + 8;
#pragma unroll
                for (int j = 0; j < 8; j++) {
                    int cA = c0 + j * 8 + 2 * tig;
                    if (cA     > r0) p[j][0] = MASKV;
                    if (cA + 1 > r0) p[j][1] = MASKV;
                    if (cA     > r1) p[j][2] = MASKV;
                    if (cA + 1 > r1) p[j][3] = MASKV;
                }
            }

            float mt0 = MASKV, mt1 = MASKV;
#pragma unroll
            for (int j = 0; j < 8; j++) {
                mt0 = fmaxf(mt0, fmaxf(p[j][0], p[j][1]));
                mt1 = fmaxf(mt1, fmaxf(p[j][2], p[j][3]));
            }
            mt0 = fmaxf(mt0, __shfl_xor_sync(0xffffffffu, mt0, 1));
            mt0 = fmaxf(mt0, __shfl_xor_sync(0xffffffffu, mt0, 2));
            mt1 = fmaxf(mt1, __shfl_xor_sync(0xffffffffu, mt1, 1));
            mt1 = fmaxf(mt1, __shfl_xor_sync(0xffffffffu, mt1, 2));

            float mnew0 = fmaxf(mrun0, mt0);
            float mnew1 = fmaxf(mrun1, mt1);
            float corr0, corr1;
            {
                float d0 = fmaxf(mrun0 - mnew0, -126.0f);
                float d1 = fmaxf(mrun1 - mnew1, -126.0f);
                asm("ex2.approx.f32 %0, %1;" : "=f"(corr0) : "f"(d0));
                asm("ex2.approx.f32 %0, %1;" : "=f"(corr1) : "f"(d1));
            }
            mrun0 = mnew0; mrun1 = mnew1;

            unsigned pf[8][2];
#pragma unroll
            for (int j = 0; j < 8; j++) {
                float y0 = fmaxf(p[j][0] - mnew0, YCLAMP);
                float y1 = fmaxf(p[j][1] - mnew0, YCLAMP);
                float y2 = fmaxf(p[j][2] - mnew1, YCLAMP);
                float y3 = fmaxf(p[j][3] - mnew1, YCLAMP);
                unsigned t0, t1;
                asm("cvt.rn.f16x2.f32 %0, %1, %2;" : "=r"(t0) : "f"(y1), "f"(y0));
                asm("cvt.rn.f16x2.f32 %0, %1, %2;" : "=r"(t1) : "f"(y3), "f"(y2));
                asm("ex2.approx.f16x2 %0, %0;" : "+r"(t0));
                asm("ex2.approx.f16x2 %0, %0;" : "+r"(t1));
                pf[j][0] = t0;
                pf[j][1] = t1;
                o[j][0] *= corr0; o[j][1] *= corr0;
                o[j][2] *= corr1; o[j][3] *= corr1;
            }

            float ltmp[4] = {0.0f, 0.0f, 0.0f, 0.0f};
            const unsigned ones2[2] = {0x3C003C00u, 0x3C003C00u};
#pragma unroll
            for (int kc = 0; kc < 4; kc++) {
                unsigned pa[4] = {pf[2 * kc][0], pf[2 * kc][1],
                                  pf[2 * kc + 1][0], pf[2 * kc + 1][1]};
                mma16816h(ltmp, pa, ones2);
#pragma unroll
                for (int j = 0; j < 8; j++) {
                    int bbase = (j * 8 + g) * STR + kc * 8 + tig;
                    unsigned bh[2] = {VHI[bbase], VHI[bbase + 4]};
                    unsigned bl[2] = {VLO[bbase], VLO[bbase + 4]};
                    mma16816h(o[j], pa, bh);
                    mma16816h(o[j], pa, bl);
                }
            }
            lrun0 = lrun0 * corr0 + ltmp[0];
            lrun1 = lrun1 * corr1 + ltmp[2];
        }

        __syncthreads();
        if (kt + 2 < nkt) {
            fillKV(kt & 1, c0 + 128);
            cp_commit();
        }
    }

    float inv0 = 1.0f / lrun0;
    float inv1 = 1.0f / lrun1;
#pragma unroll
    for (int j = 0; j < 8; j++) {
        int dh = j * 8 + 2 * tig;
        size_t r0 = ((size_t)b * SS + wrow + g) * DD + h * DH + dh;
        size_t r1 = ((size_t)b * SS + wrow + g + 8) * DD + h * DH + dh;
        unsigned h0, l0, h1, l1;
        split2h(o[j][0] * inv0, o[j][1] * inv0, h0, l0);
        split2h(o[j][2] * inv1, o[j][3] * inv1, h1, l1);
        *(unsigned*)(CtxHi + r0) = h0;
        *(unsigned*)(CtxLo + r0) = l0;
        *(unsigned*)(CtxHi + r1) = h1;
        *(unsigned*)(CtxLo + r1) = l1;
    }
}

// ---------------------------------------------------------------------------
// Launch
// ---------------------------------------------------------------------------
extern "C" void kernel_launch(void* const* d_in, const int* in_sizes, int n_in,
                              void* d_out, int out_size)
{
    const float* q  = (const float*)d_in[0];
    const float* k  = (const float*)d_in[1];
    const float* v  = (const float*)d_in[2];
    // d_in[3] = mask (causal; analytic)
    const float* wq = (const float*)d_in[4];
    const float* bq = (const float*)d_in[5];
    const float* wk = (const float*)d_in[6];
    const float* bk = (const float*)d_in[7];
    const float* wv = (const float*)d_in[8];
    const float* bv = (const float*)d_in[9];
    const float* wo = (const float*)d_in[10];
    const float* bo = (const float*)d_in[11];
    float* out = (float*)d_out;

    __half *actHi, *actLo, *wHi, *wLo;
    __half *Qhi, *Qlo, *Khi, *Klo, *Vhi, *Vlo;
    cudaGetSymbolAddress((void**)&actHi, g_ActHi);
    cudaGetSymbolAddress((void**)&actLo, g_ActLo);
    cudaGetSymbolAddress((void**)&wHi,  g_WHi);
    cudaGetSymbolAddress((void**)&wLo,  g_WLo);
    cudaGetSymbolAddress((void**)&Qhi, g_Qhi);
    cudaGetSymbolAddress((void**)&Qlo, g_Qlo);
    cudaGetSymbolAddress((void**)&Khi, g_Khi);
    cudaGetSymbolAddress((void**)&Klo, g_Klo);
    cudaGetSymbolAddress((void**)&Vhi, g_Vhi);
    cudaGetSymbolAddress((void**)&Vlo, g_Vlo);

    cudaFuncSetAttribute(flash_attn_tc, cudaFuncAttributeMaxDynamicSharedMemorySize,
                         FA_SMEM);
    cudaFuncSetAttribute(gemm_v5<1>, cudaFuncAttributeMaxDynamicSharedMemorySize,
                         G_SMEM);
    cudaFuncSetAttribute(gemm_v5<0>, cudaFuncAttributeMaxDynamicSharedMemorySize,
                         G_SMEM);

    dim3 sa(((MM * DD / 4) + 255) / 256, 3);
    dim3 sw(((DD * DD / 4) + 255) / 256, 4);
    dim3 gq(DD / GBN, MM / GBM, 3);      // (8, 32, 3) = 768 CTAs fused QKV
    dim3 go(DD / GBN, MM / GBM);         // (8, 32) output projection
    dim3 fg(SS / 128, HH, BB);           // (16, 16, 4)

    const float qscale = 0.125f * 1.44269504088896f;  // 1/sqrt(DH) * log2(e)

    split_acts<<<sa, 256>>>(q, k, v, actHi, actLo);
    split_wts<<<sw, 256>>>(wq, wk, wv, wo, wHi, wLo);
    gemm_v5<1><<<gq, 512, G_SMEM>>>(actHi, actLo, wHi, wLo,
                                    bq, bk, bv, qscale, nullptr,
                                    Qhi, Qlo, Khi, Klo, Vhi, Vlo);
    flash_attn_tc<<<fg, 256, FA_SMEM>>>(Qhi, Qlo, Khi, Klo, Vhi, Vlo, actHi, actLo);
    gemm_v5<0><<<go, 512, G_SMEM>>>(actHi, actLo, wHi + 3 * WP, wLo + 3 * WP,
                                    bo, nullptr, nullptr, 1.0f, out,
                                    nullptr, nullptr, nullptr, nullptr,
                                    nullptr, nullptr);
}

// round 14
// speedup vs baseline: 1.3897x; 1.3897x over previous
#include <cuda_runtime.h>
#include <cuda_fp16.h>
#include <math.h>

// Problem constants
#define BB 4
#define SS 2048
#define DD 1024
#define HH 16
#define DH 64
#define MM (BB * SS)   // 8192

#define MASKV  (-1e4f)
#define YCLAMP (-30.0f)

#define AP ((size_t)MM * DD)   // activation plane
#define WP ((size_t)DD * DD)   // weight plane

// ---------------------------------------------------------------------------
// Scratch (device globals)
// ---------------------------------------------------------------------------
__device__ __half g_ActHi[(size_t)3 * MM * DD];   // q/k/v splits; plane0 reused for ctx
__device__ __half g_ActLo[(size_t)3 * MM * DD];
__device__ __half g_WHi[(size_t)4 * DD * DD];     // wq, wk, wv, wo
__device__ __half g_WLo[(size_t)4 * DD * DD];

__device__ __half g_Qhi[(size_t)MM * DD];
__device__ __half g_Qlo[(size_t)MM * DD];
__device__ __half g_Khi[(size_t)MM * DD];
__device__ __half g_Klo[(size_t)MM * DD];
__device__ __half g_Vhi[(size_t)MM * DD];   // V^T layout: [b][h][dh][s]
__device__ __half g_Vlo[(size_t)MM * DD];

// ---------------------------------------------------------------------------
// mma.sync m16n8k16 f16 -> fp32 ; ldmatrix
// ---------------------------------------------------------------------------
__device__ __forceinline__ void mma16816h(float* c, const unsigned* a, const unsigned* b)
{
    asm volatile(
        "mma.sync.aligned.m16n8k16.row.col.f32.f16.f16.f32 "
        "{%0,%1,%2,%3}, {%4,%5,%6,%7}, {%8,%9}, {%0,%1,%2,%3};\n"
        : "+f"(c[0]), "+f"(c[1]), "+f"(c[2]), "+f"(c[3])
        : "r"(a[0]), "r"(a[1]), "r"(a[2]), "r"(a[3]), "r"(b[0]), "r"(b[1]));
}

__device__ __forceinline__ void ldsm4(unsigned& r0, unsigned& r1, unsigned& r2,
                                      unsigned& r3, unsigned addr)
{
    asm volatile("ldmatrix.sync.aligned.m8n8.x4.shared.b16 {%0,%1,%2,%3}, [%4];\n"
                 : "=r"(r0), "=r"(r1), "=r"(r2), "=r"(r3) : "r"(addr));
}

__device__ __forceinline__ void split2h(float x, float y, unsigned& hi, unsigned& lo)
{
    __half hx = __float2half(x);
    __half hy = __float2half(y);
    float rx = x - __half2float(hx);
    float ry = y - __half2float(hy);
    __half2 H(hx, hy);
    __half2 L(__float2half(rx), __float2half(ry));
    hi = *(unsigned*)&H;
    lo = *(unsigned*)&L;
}

// cp.async helpers
__device__ __forceinline__ void cp16(unsigned saddr, const void* g)
{
    asm volatile("cp.async.cg.shared.global [%0], [%1], 16;\n" :: "r"(saddr), "l"(g));
}
__device__ __forceinline__ void cp_commit()
{
    asm volatile("cp.async.commit_group;\n");
}
template<int N> __device__ __forceinline__ void cp_wait()
{
    asm volatile("cp.async.wait_group %0;\n" :: "n"(N));
}

// ---------------------------------------------------------------------------
// Batched splits
// ---------------------------------------------------------------------------
__device__ __forceinline__ void split_store(const float* X, __half* hi, __half* lo, int i)
{
    float4 x = ((const float4*)X)[i];
    unsigned h0, l0, h1, l1;
    split2h(x.x, x.y, h0, l0);
    split2h(x.z, x.w, h1, l1);
    unsigned* H = (unsigned*)(hi + (size_t)i * 4);
    unsigned* L = (unsigned*)(lo + (size_t)i * 4);
    H[0] = h0; H[1] = h1;
    L[0] = l0; L[1] = l1;
}

__global__ __launch_bounds__(256) void split_acts(
    const float* __restrict__ q, const float* __restrict__ k,
    const float* __restrict__ v, __half* __restrict__ hi, __half* __restrict__ lo)
{
    int i = blockIdx.x * blockDim.x + threadIdx.x;
    int n4 = (MM * DD) / 4;
    if (i >= n4) return;
    int z = blockIdx.y;
    const float* src = (z == 0) ? q : (z == 1) ? k : v;
    split_store(src, hi + (size_t)z * MM * DD, lo + (size_t)z * MM * DD, i);
}

__global__ __launch_bounds__(256) void split_wts(
    const float* __restrict__ w0, const float* __restrict__ w1,
    const float* __restrict__ w2, const float* __restrict__ w3,
    __half* __restrict__ hi, __half* __restrict__ lo)
{
    int i = blockIdx.x * blockDim.x + threadIdx.x;
    int n4 = (DD * DD) / 4;
    if (i >= n4) return;
    int z = blockIdx.y;
    const float* src = (z == 0) ? w0 : (z == 1) ? w1 : (z == 2) ? w2 : w3;
    split_store(src, hi + (size_t)z * DD * DD, lo + (size_t)z * DD * DD, i);
}

// ---------------------------------------------------------------------------
// Split-f16 tensor-core GEMM v4 (reverted to R10 — best measured 207us):
// BM=256, BN=128, BK=16, 512 threads, ldmatrix fragments, 2-stage cp.async.
// MODE 0: fp32 C. MODE 1: f16 hi/lo row-major. MODE 2: f16 hi/lo V^T.
// ---------------------------------------------------------------------------
#define GBM 256
#define GBN 128
#define GBUF 36864       // bytes per stage: A 2*12288 + W 2*6144
#define G_ALO 12288
#define G_WHI 24576
#define G_WLO 30720
#define G_SMEM (2 * GBUF)

template<int MODE>
__global__ __launch_bounds__(512) void gemm_f16split(
    const __half* __restrict__ Ahi, const __half* __restrict__ Alo,
    const __half* __restrict__ Whi, const __half* __restrict__ Wlo,
    const float* __restrict__ bias, float scale,
    float* __restrict__ C, __half* __restrict__ Chi, __half* __restrict__ Clo)
{
    extern __shared__ __align__(16) char gsm[];
    const unsigned sbase = (unsigned)__cvta_generic_to_shared(gsm);

    const int tid  = threadIdx.x;
    const int wid  = tid >> 5;
    const int lane = tid & 31;
    const int g    = lane >> 2;
    const int tig  = lane & 3;
    const int wr   = wid >> 2;
    const int wc   = wid & 3;
    const int m0   = blockIdx.y * GBM;
    const int n0   = blockIdx.x * GBN;

    float acc[4][4][4];
#pragma unroll
    for (int mt = 0; mt < 4; mt++)
#pragma unroll
        for (int nt = 0; nt < 4; nt++)
#pragma unroll
            for (int i = 0; i < 4; i++) acc[mt][nt][i] = 0.0f;

    unsigned aoff[4];
#pragma unroll
    for (int mt = 0; mt < 4; mt++)
        aoff[mt] = (unsigned)((wr * 64 + mt * 16 + (lane & 15)) * 48
                              + (lane >> 4) * 16);
    unsigned woff[2];
#pragma unroll
    for (int p = 0; p < 2; p++)
        woff[p] = (unsigned)((wc * 32 + p * 16 + ((lane >> 4) * 8) + (lane & 7)) * 48
                             + ((lane >> 3) & 1) * 16);

    const int ar = tid >> 1, ac = (tid & 1) * 8;
    auto fill = [&](int buf, int kt) {
        int k0 = kt * 16;
        unsigned sb = sbase + buf * GBUF;
        size_t aro = (size_t)(m0 + ar) * DD + k0 + ac;
        cp16(sb + ar * 48 + ac * 2,          Ahi + aro);
        cp16(sb + G_ALO + ar * 48 + ac * 2,  Alo + aro);
        if (tid < 256) {
            size_t wro = (size_t)(n0 + ar) * DD + k0 + ac;
            cp16(sb + G_WHI + ar * 48 + ac * 2, Whi + wro);
            cp16(sb + G_WLO + ar * 48 + ac * 2, Wlo + wro);
        }
    };

    fill(0, 0); cp_commit();
    fill(1, 1); cp_commit();

    for (int kt = 0; kt < 64; kt++) {
        cp_wait<1>();
        __syncthreads();

        unsigned sb = sbase + (kt & 1) * GBUF;

        unsigned af[4][4], bh[4][2], bl[4][2];
#pragma unroll
        for (int mt = 0; mt < 4; mt++)
            ldsm4(af[mt][0], af[mt][1], af[mt][2], af[mt][3], sb + aoff[mt]);
        ldsm4(bh[0][0], bh[0][1], bh[1][0], bh[1][1], sb + G_WHI + woff[0]);
        ldsm4(bh[2][0], bh[2][1], bh[3][0], bh[3][1], sb + G_WHI + woff[1]);
#pragma unroll
        for (int mt = 0; mt < 4; mt++)
#pragma unroll
            for (int nt = 0; nt < 4; nt++)
                mma16816h(acc[mt][nt], af[mt], bh[nt]);
        ldsm4(bl[0][0], bl[0][1], bl[1][0], bl[1][1], sb + G_WLO + woff[0]);
        ldsm4(bl[2][0], bl[2][1], bl[3][0], bl[3][1], sb + G_WLO + woff[1]);
#pragma unroll
        for (int mt = 0; mt < 4; mt++)
#pragma unroll
            for (int nt = 0; nt < 4; nt++)
                mma16816h(acc[mt][nt], af[mt], bl[nt]);
#pragma unroll
        for (int mt = 0; mt < 4; mt++)
            ldsm4(af[mt][0], af[mt][1], af[mt][2], af[mt][3], sb + G_ALO + aoff[mt]);
#pragma unroll
        for (int mt = 0; mt < 4; mt++)
#pragma unroll
            for (int nt = 0; nt < 4; nt++)
                mma16816h(acc[mt][nt], af[mt], bh[nt]);

        __syncthreads();
        if (kt + 2 < 64) {
            fill(kt & 1, kt + 2);
            cp_commit();
        }
    }

    // Epilogue
#pragma unroll
    for (int mt = 0; mt < 4; mt++) {
        int row = m0 + wr * 64 + mt * 16 + g;
#pragma unroll
        for (int nt = 0; nt < 4; nt++) {
            int col = n0 + wc * 32 + nt * 8 + 2 * tig;
            float b0 = bias[col], b1 = bias[col + 1];
            float v0 = (acc[mt][nt][0] + b0) * scale;
            float v1 = (acc[mt][nt][1] + b1) * scale;
            float v2 = (acc[mt][nt][2] + b0) * scale;
            float v3 = (acc[mt][nt][3] + b1) * scale;
            if (MODE == 0) {
                *(float2*)&C[(size_t)row * DD + col] = make_float2(v0, v1);
                *(float2*)&C[(size_t)(row + 8) * DD + col] = make_float2(v2, v3);
            } else if (MODE == 1) {
                unsigned h01, l01, h23, l23;
                split2h(v0, v1, h01, l01);
                split2h(v2, v3, h23, l23);
                *(unsigned*)(Chi + (size_t)row * DD + col) = h01;
                *(unsigned*)(Clo + (size_t)row * DD + col) = l01;
                *(unsigned*)(Chi + (size_t)(row + 8) * DD + col) = h23;
                *(unsigned*)(Clo + (size_t)(row + 8) * DD + col) = l23;
            } else {
                float vv[4] = {v0, v1, v2, v3};
                int rr[4] = {row, row, row + 8, row + 8};
                int cc[4] = {col, col + 1, col, col + 1};
#pragma unroll
                for (int e = 0; e < 4; e++) {
                    int bq = rr[e] >> 11, s = rr[e] & 2047;
                    int hh = cc[e] >> 6,  dh = cc[e] & 63;
                    size_t di = (((size_t)bq * HH + hh) * DH + dh) * SS + s;
                    __half hx = __float2half(vv[e]);
                    Chi[di] = hx;
                    Clo[di] = __float2half(vv[e] - __half2float(hx));
                }
            }
        }
    }
}

// ---------------------------------------------------------------------------
// Pipelined tensor-core causal flash attention, v2: ldmatrix fragment loads.
// Grid: (S/128, H, B). Block: 256 (8 warps). K/V 64-key tiles, 2-buffer cp.async.
// smem rows: 144 B stride (72 halves) everywhere.
// ---------------------------------------------------------------------------
#define FA_SMEM 110592
#define STR 36

__global__ __launch_bounds__(256) void flash_attn_tc(
    const __half* __restrict__ Qhi_, const __half* __restrict__ Qlo_,
    const __half* __restrict__ Khi_, const __half* __restrict__ Klo_,
    const __half* __restrict__ VhiT_, const __half* __restrict__ VloT_,
    __half* __restrict__ CtxHi, __half* __restrict__ CtxLo)
{
    extern __shared__ __align__(16) char smraw[];
    const unsigned sbase = (unsigned)__cvta_generic_to_shared(smraw);

    const int tid  = threadIdx.x;
    const int w    = tid >> 5;
    const int lane = tid & 31;
    const int g    = lane >> 2;
    const int tig  = lane & 3;
    const int qt   = blockIdx.x;
    const int h    = blockIdx.y;
    const int b    = blockIdx.z;
    const int s0   = qt * 128;

    const size_t base   = ((size_t)b * SS) * DD + (size_t)h * DH;
    const size_t vtbase = ((size_t)(b * HH + h)) * DH * SS;

    const int wrow = s0 + w * 16;
    const int nkt  = 2 * (qt + 1);

    // ldmatrix lane offsets (byte, row stride 144)
    const unsigned qoff = (unsigned)((w * 16 + (lane & 15)) * 144 + (lane >> 4) * 16);
    unsigned boff[4];   // K/V paired-B fragment offsets (j-pairs 0..3)
#pragma unroll
    for (int jp = 0; jp < 4; jp++)
        boff[jp] = (unsigned)((jp * 16 + ((lane >> 4) * 8) + (lane & 7)) * 144
                              + ((lane >> 3) & 1) * 16);

    // ---- Q fill via cp.async ----
    {
        int row = tid >> 1, hf = tid & 1;
        const __half* srcH = Qhi_ + base + (size_t)(s0 + row) * DD + hf * 32;
        const __half* srcL = Qlo_ + base + (size_t)(s0 + row) * DD + hf * 32;
        unsigned dH = sbase + (row * STR + hf * 16) * 4;
        unsigned dL = dH + 18432;
#pragma unroll
        for (int j = 0; j < 4; j++) {
            cp16(dH + j * 16, srcH + j * 8);
            cp16(dL + j * 16, srcL + j * 8);
        }
    }

    const int frow = tid >> 2;
    const int fc   = tid & 3;
    auto fillKV = [&](int buf, int c0) {
        size_t kro = base + (size_t)(c0 + frow) * DD;
        unsigned kH = sbase + 36864 + buf * 18432 + frow * 144;
        unsigned kL = kH + 9216;
        cp16(kH + fc * 16,       Khi_ + kro + fc * 8);
        cp16(kH + (fc + 4) * 16, Khi_ + kro + (fc + 4) * 8);
        cp16(kL + fc * 16,       Klo_ + kro + fc * 8);
        cp16(kL + (fc + 4) * 16, Klo_ + kro + (fc + 4) * 8);
        size_t vro = vtbase + (size_t)frow * SS + c0;
        unsigned vH = sbase + 73728 + buf * 18432 + frow * 144;
        unsigned vL = vH + 9216;
        cp16(vH + fc * 16,       VhiT_ + vro + fc * 8);
        cp16(vH + (fc + 4) * 16, VhiT_ + vro + (fc + 4) * 8);
        cp16(vL + fc * 16,       VloT_ + vro + fc * 8);
        cp16(vL + (fc + 4) * 16, VloT_ + vro + (fc + 4) * 8);
    };

    fillKV(0, 0);
    cp_commit();
    if (nkt > 1) fillKV(1, 64);
    cp_commit();

    float o[8][4];
    float mrun0 = MASKV, mrun1 = MASKV;
    float lrun0 = 0.0f,  lrun1 = 0.0f;
#pragma unroll
    for (int j = 0; j < 8; j++)
#pragma unroll
        for (int e = 0; e < 4; e++) o[j][e] = 0.0f;

    for (int kt = 0; kt < nkt; kt++) {
        const int c0 = kt * 64;
        if (kt + 1 < nkt) cp_wait<1>(); else cp_wait<0>();
        __syncthreads();

        const unsigned kbase = sbase + 36864 + (kt & 1) * 18432;
        const unsigned vbase = sbase + 73728 + (kt & 1) * 18432;

        if (c0 <= wrow + 15) {
            // ---- S = Q K^T (3-term split, ldmatrix fragments) ----
            float p[8][4];
#pragma unroll
            for (int j = 0; j < 8; j++)
#pragma unroll
                for (int e = 0; e < 4; e++) p[j][e] = 0.0f;

#pragma unroll
            for (int kc = 0; kc < 4; kc++) {
                unsigned ah[4], al[4];
                ldsm4(ah[0], ah[1], ah[2], ah[3], sbase + qoff + kc * 32);
                ldsm4(al[0], al[1], al[2], al[3], sbase + 18432 + qoff + kc * 32);
#pragma unroll
                for (int jp = 0; jp < 4; jp++) {
                    unsigned kh[4], kl[4];
                    ldsm4(kh[0], kh[1], kh[2], kh[3], kbase + boff[jp] + kc * 32);
                    ldsm4(kl[0], kl[1], kl[2], kl[3], kbase + 9216 + boff[jp] + kc * 32);
                    mma16816h(p[2 * jp],     ah, kh);
                    mma16816h(p[2 * jp],     ah, kl);
                    mma16816h(p[2 * jp],     al, kh);
                    mma16816h(p[2 * jp + 1], ah, kh + 2);
                    mma16816h(p[2 * jp + 1], ah, kl + 2);
                    mma16816h(p[2 * jp + 1], al, kh + 2);
                }
            }

            // ---- causal mask ----
            if (c0 + 63 > wrow) {
                int r0 = wrow + g, r1 = wrow + g + 8;
#pragma unroll
                for (int j = 0; j < 8; j++) {
                    int cA = c0 + j * 8 + 2 * tig;
                    if (cA     > r0) p[j][0] = MASKV;
                    if (cA + 1 > r0) p[j][1] = MASKV;
                    if (cA     > r1) p[j][2] = MASKV;
                    if (cA + 1 > r1) p[j][3] = MASKV;
                }
            }

            // ---- row max ----
            float mt0 = MASKV, mt1 = MASKV;
#pragma unroll
            for (int j = 0; j < 8; j++) {
                mt0 = fmaxf(mt0, fmaxf(p[j][0], p[j][1]));
                mt1 = fmaxf(mt1, fmaxf(p[j][2], p[j][3]));
            }
            mt0 = fmaxf(mt0, __shfl_xor_sync(0xffffffffu, mt0, 1));
            mt0 = fmaxf(mt0, __shfl_xor_sync(0xffffffffu, mt0, 2));
            mt1 = fmaxf(mt1, __shfl_xor_sync(0xffffffffu, mt1, 1));
            mt1 = fmaxf(mt1, __shfl_xor_sync(0xffffffffu, mt1, 2));

            float mnew0 = fmaxf(mrun0, mt0);
            float mnew1 = fmaxf(mrun1, mt1);
            float corr0, corr1;
            {
                float d0 = fmaxf(mrun0 - mnew0, -126.0f);
                float d1 = fmaxf(mrun1 - mnew1, -126.0f);
                asm("ex2.approx.f32 %0, %1;" : "=f"(corr0) : "f"(d0));
                asm("ex2.approx.f32 %0, %1;" : "=f"(corr1) : "f"(d1));
            }
            mrun0 = mnew0; mrun1 = mnew1;

            // ---- p = 2^(clamp(s-m)) via f16x2 MUFU ----
            unsigned pf[8][2];
#pragma unroll
            for (int j = 0; j < 8; j++) {
                float y0 = fmaxf(p[j][0] - mnew0, YCLAMP);
                float y1 = fmaxf(p[j][1] - mnew0, YCLAMP);
                float y2 = fmaxf(p[j][2] - mnew1, YCLAMP);
                float y3 = fmaxf(p[j][3] - mnew1, YCLAMP);
                unsigned t0, t1;
                asm("cvt.rn.f16x2.f32 %0, %1, %2;" : "=r"(t0) : "f"(y1), "f"(y0));
                asm("cvt.rn.f16x2.f32 %0, %1, %2;" : "=r"(t1) : "f"(y3), "f"(y2));
                asm("ex2.approx.f16x2 %0, %0;" : "+r"(t0));
                asm("ex2.approx.f16x2 %0, %0;" : "+r"(t1));
                pf[j][0] = t0;
                pf[j][1] = t1;
                o[j][0] *= corr0; o[j][1] *= corr0;
                o[j][2] *= corr1; o[j][3] *= corr1;
            }

            // ---- O += P V (ldmatrix V fragments); l via ones MMA ----
            float ltmp[4] = {0.0f, 0.0f, 0.0f, 0.0f};
            const unsigned ones2[2] = {0x3C003C00u, 0x3C003C00u};
#pragma unroll
            for (int kc = 0; kc < 4; kc++) {
                unsigned pa[4] = {pf[2 * kc][0], pf[2 * kc][1],
                                  pf[2 * kc + 1][0], pf[2 * kc + 1][1]};
                mma16816h(ltmp, pa, ones2);
#pragma unroll
                for (int jp = 0; jp < 4; jp++) {
                    unsigned vh[4], vl[4];
                    ldsm4(vh[0], vh[1], vh[2], vh[3], vbase + boff[jp] + kc * 32);
                    ldsm4(vl[0], vl[1], vl[2], vl[3], vbase + 9216 + boff[jp] + kc * 32);
                    mma16816h(o[2 * jp],     pa, vh);
                    mma16816h(o[2 * jp],     pa, vl);
                    mma16816h(o[2 * jp + 1], pa, vh + 2);
                    mma16816h(o[2 * jp + 1], pa, vl + 2);
                }
            }
            lrun0 = lrun0 * corr0 + ltmp[0];
            lrun1 = lrun1 * corr1 + ltmp[2];
        }

        __syncthreads();
        if (kt + 2 < nkt) {
            fillKV(kt & 1, c0 + 128);
            cp_commit();
        }
    }

    float inv0 = 1.0f / lrun0;
    float inv1 = 1.0f / lrun1;
#pragma unroll
    for (int j = 0; j < 8; j++) {
        int dh = j * 8 + 2 * tig;
        size_t r0 = ((size_t)b * SS + wrow + g) * DD + h * DH + dh;
        size_t r1 = ((size_t)b * SS + wrow + g + 8) * DD + h * DH + dh;
        unsigned h0, l0, h1, l1;
        split2h(o[j][0] * inv0, o[j][1] * inv0, h0, l0);
        split2h(o[j][2] * inv1, o[j][3] * inv1, h1, l1);
        *(unsigned*)(CtxHi + r0) = h0;
        *(unsigned*)(CtxLo + r0) = l0;
        *(unsigned*)(CtxHi + r1) = h1;
        *(unsigned*)(CtxLo + r1) = l1;
    }
}

// ---------------------------------------------------------------------------
// Launch
// ---------------------------------------------------------------------------
extern "C" void kernel_launch(void* const* d_in, const int* in_sizes, int n_in,
                              void* d_out, int out_size)
{
    const float* q  = (const float*)d_in[0];
    const float* k  = (const float*)d_in[1];
    const float* v  = (const float*)d_in[2];
    // d_in[3] = mask (causal; analytic)
    const float* wq = (const float*)d_in[4];
    const float* bq = (const float*)d_in[5];
    const float* wk = (const float*)d_in[6];
    const float* bk = (const float*)d_in[7];
    const float* wv = (const float*)d_in[8];
    const float* bv = (const float*)d_in[9];
    const float* wo = (const float*)d_in[10];
    const float* bo = (const float*)d_in[11];
    float* out = (float*)d_out;

    __half *actHi, *actLo, *wHi, *wLo;
    __half *Qhi, *Qlo, *Khi, *Klo, *Vhi, *Vlo;
    cudaGetSymbolAddress((void**)&actHi, g_ActHi);
    cudaGetSymbolAddress((void**)&actLo, g_ActLo);
    cudaGetSymbolAddress((void**)&wHi,  g_WHi);
    cudaGetSymbolAddress((void**)&wLo,  g_WLo);
    cudaGetSymbolAddress((void**)&Qhi, g_Qhi);
    cudaGetSymbolAddress((void**)&Qlo, g_Qlo);
    cudaGetSymbolAddress((void**)&Khi, g_Khi);
    cudaGetSymbolAddress((void**)&Klo, g_Klo);
    cudaGetSymbolAddress((void**)&Vhi, g_Vhi);
    cudaGetSymbolAddress((void**)&Vlo, g_Vlo);

    cudaFuncSetAttribute(flash_attn_tc, cudaFuncAttributeMaxDynamicSharedMemorySize,
                         FA_SMEM);
    cudaFuncSetAttribute(gemm_f16split<0>, cudaFuncAttributeMaxDynamicSharedMemorySize,
                         G_SMEM);
    cudaFuncSetAttribute(gemm_f16split<1>, cudaFuncAttributeMaxDynamicSharedMemorySize,
                         G_SMEM);
    cudaFuncSetAttribute(gemm_f16split<2>, cudaFuncAttributeMaxDynamicSharedMemorySize,
                         G_SMEM);

    dim3 sa(((MM * DD / 4) + 255) / 256, 3);
    dim3 sw(((DD * DD / 4) + 255) / 256, 4);
    dim3 gg(DD / GBN, MM / GBM);         // (8, 32)
    dim3 fg(SS / 128, HH, BB);           // (16, 16, 4)

    const float qscale = 0.125f * 1.44269504088896f;  // 1/sqrt(DH) * log2(e)

    split_acts<<<sa, 256>>>(q, k, v, actHi, actLo);
    split_wts<<<sw, 256>>>(wq, wk, wv, wo, wHi, wLo);
    gemm_f16split<1><<<gg, 512, G_SMEM>>>(actHi, actLo, wHi, wLo, bq, qscale,
                                          nullptr, Qhi, Qlo);
    gemm_f16split<1><<<gg, 512, G_SMEM>>>(actHi + AP, actLo + AP, wHi + WP, wLo + WP,
                                          bk, 1.0f, nullptr, Khi, Klo);
    gemm_f16split<2><<<gg, 512, G_SMEM>>>(actHi + 2 * AP, actLo + 2 * AP,
                                          wHi + 2 * WP, wLo + 2 * WP,
                                          bv, 1.0f, nullptr, Vhi, Vlo);
    flash_attn_tc<<<fg, 256, FA_SMEM>>>(Qhi, Qlo, Khi, Klo, Vhi, Vlo, actHi, actLo);
    gemm_f16split<0><<<gg, 512, G_SMEM>>>(actHi, actLo, wHi + 3 * WP, wLo + 3 * WP,
                                          bo, 1.0f, out, nullptr, nullptr);
}

// round 15
// speedup vs baseline: 1.5092x; 1.0860x over previous
#include <cuda_runtime.h>
#include <cuda_fp16.h>
#include <math.h>

// Problem constants
#define BB 4
#define SS 2048
#define DD 1024
#define HH 16
#define DH 64
#define MM (BB * SS)   // 8192

#define MASKV  (-1e4f)
#define YCLAMP (-30.0f)

#define AP ((size_t)MM * DD)   // activation plane
#define WP ((size_t)DD * DD)   // weight plane

// ---------------------------------------------------------------------------
// Scratch (device globals)
// ---------------------------------------------------------------------------
__device__ __half g_ActHi[(size_t)3 * MM * DD];   // q/k/v splits; plane0 reused for ctx
__device__ __half g_ActLo[(size_t)3 * MM * DD];
__device__ __half g_WHi[(size_t)4 * DD * DD];     // wq, wk, wv, wo
__device__ __half g_WLo[(size_t)4 * DD * DD];

__device__ __half g_Qhi[(size_t)MM * DD];
__device__ __half g_Qlo[(size_t)MM * DD];
__device__ __half g_Khi[(size_t)MM * DD];
__device__ __half g_Klo[(size_t)MM * DD];
__device__ __half g_Vhi[(size_t)MM * DD];   // V^T layout: [b][h][dh][s]
__device__ __half g_Vlo[(size_t)MM * DD];

// ---------------------------------------------------------------------------
// mma.sync m16n8k16 f16 -> fp32 ; ldmatrix
// ---------------------------------------------------------------------------
__device__ __forceinline__ void mma16816h(float* c, const unsigned* a, const unsigned* b)
{
    asm volatile(
        "mma.sync.aligned.m16n8k16.row.col.f32.f16.f16.f32 "
        "{%0,%1,%2,%3}, {%4,%5,%6,%7}, {%8,%9}, {%0,%1,%2,%3};\n"
        : "+f"(c[0]), "+f"(c[1]), "+f"(c[2]), "+f"(c[3])
        : "r"(a[0]), "r"(a[1]), "r"(a[2]), "r"(a[3]), "r"(b[0]), "r"(b[1]));
}

__device__ __forceinline__ void ldsm4(unsigned& r0, unsigned& r1, unsigned& r2,
                                      unsigned& r3, unsigned addr)
{
    asm volatile("ldmatrix.sync.aligned.m8n8.x4.shared.b16 {%0,%1,%2,%3}, [%4];\n"
                 : "=r"(r0), "=r"(r1), "=r"(r2), "=r"(r3) : "r"(addr));
}

__device__ __forceinline__ void split2h(float x, float y, unsigned& hi, unsigned& lo)
{
    __half hx = __float2half(x);
    __half hy = __float2half(y);
    float rx = x - __half2float(hx);
    float ry = y - __half2float(hy);
    __half2 H(hx, hy);
    __half2 L(__float2half(rx), __float2half(ry));
    hi = *(unsigned*)&H;
    lo = *(unsigned*)&L;
}

// cp.async helpers
__device__ __forceinline__ void cp16(unsigned saddr, const void* g)
{
    asm volatile("cp.async.cg.shared.global [%0], [%1], 16;\n" :: "r"(saddr), "l"(g));
}
__device__ __forceinline__ void cp_commit()
{
    asm volatile("cp.async.commit_group;\n");
}
template<int N> __device__ __forceinline__ void cp_wait()
{
    asm volatile("cp.async.wait_group %0;\n" :: "n"(N));
}

// ---------------------------------------------------------------------------
// Batched splits
// ---------------------------------------------------------------------------
__device__ __forceinline__ void split_store(const float* X, __half* hi, __half* lo, int i)
{
    float4 x = ((const float4*)X)[i];
    unsigned h0, l0, h1, l1;
    split2h(x.x, x.y, h0, l0);
    split2h(x.z, x.w, h1, l1);
    unsigned* H = (unsigned*)(hi + (size_t)i * 4);
    unsigned* L = (unsigned*)(lo + (size_t)i * 4);
    H[0] = h0; H[1] = h1;
    L[0] = l0; L[1] = l1;
}

__global__ __launch_bounds__(256) void split_acts(
    const float* __restrict__ q, const float* __restrict__ k,
    const float* __restrict__ v, __half* __restrict__ hi, __half* __restrict__ lo)
{
    int i = blockIdx.x * blockDim.x + threadIdx.x;
    int n4 = (MM * DD) / 4;
    if (i >= n4) return;
    int z = blockIdx.y;
    const float* src = (z == 0) ? q : (z == 1) ? k : v;
    split_store(src, hi + (size_t)z * MM * DD, lo + (size_t)z * MM * DD, i);
}

__global__ __launch_bounds__(256) void split_wts(
    const float* __restrict__ w0, const float* __restrict__ w1,
    const float* __restrict__ w2, const float* __restrict__ w3,
    __half* __restrict__ hi, __half* __restrict__ lo)
{
    int i = blockIdx.x * blockDim.x + threadIdx.x;
    int n4 = (DD * DD) / 4;
    if (i >= n4) return;
    int z = blockIdx.y;
    const float* src = (z == 0) ? w0 : (z == 1) ? w1 : (z == 2) ? w2 : w3;
    split_store(src, hi + (size_t)z * DD * DD, lo + (size_t)z * DD * DD, i);
}

// ---------------------------------------------------------------------------
// Split-f16 tensor-core GEMM v6: v4 skeleton with BK=32 (half the barriers).
// BM=256, BN=128, BK=32, 512 threads, ldmatrix fragments, 2-stage cp.async.
// Row stride 80 B (40 halves) — ldmatrix conflict-free (banks 20r mod 32).
// MODE 0: fp32 C. MODE 1: f16 hi/lo row-major. MODE 2: f16 hi/lo V^T.
// ---------------------------------------------------------------------------
#define GBM 256
#define GBN 128
#define GSTR 80          // bytes per smem row
#define GA_LO 20480
#define GW_HI 40960
#define GW_LO 51200
#define GBUF 61440       // bytes per stage
#define G_SMEM (2 * GBUF)   // 122880

template<int MODE>
__global__ __launch_bounds__(512) void gemm_f16split(
    const __half* __restrict__ Ahi, const __half* __restrict__ Alo,
    const __half* __restrict__ Whi, const __half* __restrict__ Wlo,
    const float* __restrict__ bias, float scale,
    float* __restrict__ C, __half* __restrict__ Chi, __half* __restrict__ Clo)
{
    extern __shared__ __align__(16) char gsm[];
    const unsigned sbase = (unsigned)__cvta_generic_to_shared(gsm);

    const int tid  = threadIdx.x;
    const int wid  = tid >> 5;
    const int lane = tid & 31;
    const int g    = lane >> 2;
    const int tig  = lane & 3;
    const int wr   = wid >> 2;    // 0..3 : 64-row group
    const int wc   = wid & 3;     // 0..3 : 32-col group
    const int m0   = blockIdx.y * GBM;
    const int n0   = blockIdx.x * GBN;

    float acc[4][4][4];
#pragma unroll
    for (int mt = 0; mt < 4; mt++)
#pragma unroll
        for (int nt = 0; nt < 4; nt++)
#pragma unroll
            for (int i = 0; i < 4; i++) acc[mt][nt][i] = 0.0f;

    // ldmatrix per-lane byte offsets (row stride 80 B); add ks*32 at use
    unsigned aoff[4];
#pragma unroll
    for (int mt = 0; mt < 4; mt++)
        aoff[mt] = (unsigned)((wr * 64 + mt * 16 + (lane & 15)) * GSTR
                              + (lane >> 4) * 16);
    unsigned woff[2];
#pragma unroll
    for (int p = 0; p < 2; p++)
        woff[p] = (unsigned)((wc * 32 + p * 16 + ((lane >> 4) * 8) + (lane & 7)) * GSTR
                             + ((lane >> 3) & 1) * 16);

    // fill mapping: A rows 256 x 64B (4 chunks) -> 2 chunks/thread/array
    //               W rows 128 x 64B (4 chunks) -> 1 chunk/thread/array
    const int ar  = tid >> 1, ac2 = (tid & 1) * 2;
    const int wrj = tid >> 2, wc4 = tid & 3;
    auto fill = [&](int buf, int kt) {
        int k0 = kt * 32;
        unsigned sb = sbase + buf * GBUF;
        size_t aro = (size_t)(m0 + ar) * DD + k0 + ac2 * 8;
        unsigned sa_ = sb + ar * GSTR + ac2 * 16;
        cp16(sa_,      Ahi + aro);
        cp16(sa_ + 16, Ahi + aro + 8);
        cp16(sa_ + GA_LO,      Alo + aro);
        cp16(sa_ + GA_LO + 16, Alo + aro + 8);
        size_t wro = (size_t)(n0 + wrj) * DD + k0 + wc4 * 8;
        unsigned sw_ = sb + GW_HI + wrj * GSTR + wc4 * 16;
        cp16(sw_,                      Whi + wro);
        cp16(sw_ + (GW_LO - GW_HI),    Wlo + wro);
    };

    fill(0, 0); cp_commit();
    fill(1, 1); cp_commit();

    for (int kt = 0; kt < 32; kt++) {
        cp_wait<1>();
        __syncthreads();

        unsigned sb = sbase + (kt & 1) * GBUF;

#pragma unroll
        for (int ks = 0; ks < 2; ks++) {
            const unsigned ko = ks * 32;
            unsigned af[4][4], bh[4][2], bl[4][2];
#pragma unroll
            for (int mt = 0; mt < 4; mt++)
                ldsm4(af[mt][0], af[mt][1], af[mt][2], af[mt][3],
                      sb + aoff[mt] + ko);
            ldsm4(bh[0][0], bh[0][1], bh[1][0], bh[1][1], sb + GW_HI + woff[0] + ko);
            ldsm4(bh[2][0], bh[2][1], bh[3][0], bh[3][1], sb + GW_HI + woff[1] + ko);
#pragma unroll
            for (int mt = 0; mt < 4; mt++)
#pragma unroll
                for (int nt = 0; nt < 4; nt++)
                    mma16816h(acc[mt][nt], af[mt], bh[nt]);
            ldsm4(bl[0][0], bl[0][1], bl[1][0], bl[1][1], sb + GW_LO + woff[0] + ko);
            ldsm4(bl[2][0], bl[2][1], bl[3][0], bl[3][1], sb + GW_LO + woff[1] + ko);
#pragma unroll
            for (int mt = 0; mt < 4; mt++)
#pragma unroll
                for (int nt = 0; nt < 4; nt++)
                    mma16816h(acc[mt][nt], af[mt], bl[nt]);
#pragma unroll
            for (int mt = 0; mt < 4; mt++)
                ldsm4(af[mt][0], af[mt][1], af[mt][2], af[mt][3],
                      sb + GA_LO + aoff[mt] + ko);
#pragma unroll
            for (int mt = 0; mt < 4; mt++)
#pragma unroll
                for (int nt = 0; nt < 4; nt++)
                    mma16816h(acc[mt][nt], af[mt], bh[nt]);
        }

        __syncthreads();
        if (kt + 2 < 32) {
            fill(kt & 1, kt + 2);
            cp_commit();
        }
    }

    // Epilogue
#pragma unroll
    for (int mt = 0; mt < 4; mt++) {
        int row = m0 + wr * 64 + mt * 16 + g;
#pragma unroll
        for (int nt = 0; nt < 4; nt++) {
            int col = n0 + wc * 32 + nt * 8 + 2 * tig;
            float b0 = bias[col], b1 = bias[col + 1];
            float v0 = (acc[mt][nt][0] + b0) * scale;
            float v1 = (acc[mt][nt][1] + b1) * scale;
            float v2 = (acc[mt][nt][2] + b0) * scale;
            float v3 = (acc[mt][nt][3] + b1) * scale;
            if (MODE == 0) {
                *(float2*)&C[(size_t)row * DD + col] = make_float2(v0, v1);
                *(float2*)&C[(size_t)(row + 8) * DD + col] = make_float2(v2, v3);
            } else if (MODE == 1) {
                unsigned h01, l01, h23, l23;
                split2h(v0, v1, h01, l01);
                split2h(v2, v3, h23, l23);
                *(unsigned*)(Chi + (size_t)row * DD + col) = h01;
                *(unsigned*)(Clo + (size_t)row * DD + col) = l01;
                *(unsigned*)(Chi + (size_t)(row + 8) * DD + col) = h23;
                *(unsigned*)(Clo + (size_t)(row + 8) * DD + col) = l23;
            } else {
                float vv[4] = {v0, v1, v2, v3};
                int rr[4] = {row, row, row + 8, row + 8};
                int cc[4] = {col, col + 1, col, col + 1};
#pragma unroll
                for (int e = 0; e < 4; e++) {
                    int bq = rr[e] >> 11, s = rr[e] & 2047;
                    int hh = cc[e] >> 6,  dh = cc[e] & 63;
                    size_t di = (((size_t)bq * HH + hh) * DH + dh) * SS + s;
                    __half hx = __float2half(vv[e]);
                    Chi[di] = hx;
                    Clo[di] = __float2half(vv[e] - __half2float(hx));
                }
            }
        }
    }
}

// ---------------------------------------------------------------------------
// Pipelined tensor-core causal flash attention (R13, ldmatrix — unchanged).
// ---------------------------------------------------------------------------
#define FA_SMEM 110592
#define STR 36

__global__ __launch_bounds__(256) void flash_attn_tc(
    const __half* __restrict__ Qhi_, const __half* __restrict__ Qlo_,
    const __half* __restrict__ Khi_, const __half* __restrict__ Klo_,
    const __half* __restrict__ VhiT_, const __half* __restrict__ VloT_,
    __half* __restrict__ CtxHi, __half* __restrict__ CtxLo)
{
    extern __shared__ __align__(16) char smraw[];
    const unsigned sbase = (unsigned)__cvta_generic_to_shared(smraw);

    const int tid  = threadIdx.x;
    const int w    = tid >> 5;
    const int lane = tid & 31;
    const int g    = lane >> 2;
    const int tig  = lane & 3;
    const int qt   = blockIdx.x;
    const int h    = blockIdx.y;
    const int b    = blockIdx.z;
    const int s0   = qt * 128;

    const size_t base   = ((size_t)b * SS) * DD + (size_t)h * DH;
    const size_t vtbase = ((size_t)(b * HH + h)) * DH * SS;

    const int wrow = s0 + w * 16;
    const int nkt  = 2 * (qt + 1);

    const unsigned qoff = (unsigned)((w * 16 + (lane & 15)) * 144 + (lane >> 4) * 16);
    unsigned boff[4];
#pragma unroll
    for (int jp = 0; jp < 4; jp++)
        boff[jp] = (unsigned)((jp * 16 + ((lane >> 4) * 8) + (lane & 7)) * 144
                              + ((lane >> 3) & 1) * 16);

    {
        int row = tid >> 1, hf = tid & 1;
        const __half* srcH = Qhi_ + base + (size_t)(s0 + row) * DD + hf * 32;
        const __half* srcL = Qlo_ + base + (size_t)(s0 + row) * DD + hf * 32;
        unsigned dH = sbase + (row * STR + hf * 16) * 4;
        unsigned dL = dH + 18432;
#pragma unroll
        for (int j = 0; j < 4; j++) {
            cp16(dH + j * 16, srcH + j * 8);
            cp16(dL + j * 16, srcL + j * 8);
        }
    }

    const int frow = tid >> 2;
    const int fc   = tid & 3;
    auto fillKV = [&](int buf, int c0) {
        size_t kro = base + (size_t)(c0 + frow) * DD;
        unsigned kH = sbase + 36864 + buf * 18432 + frow * 144;
        unsigned kL = kH + 9216;
        cp16(kH + fc * 16,       Khi_ + kro + fc * 8);
        cp16(kH + (fc + 4) * 16, Khi_ + kro + (fc + 4) * 8);
        cp16(kL + fc * 16,       Klo_ + kro + fc * 8);
        cp16(kL + (fc + 4) * 16, Klo_ + kro + (fc + 4) * 8);
        size_t vro = vtbase + (size_t)frow * SS + c0;
        unsigned vH = sbase + 73728 + buf * 18432 + frow * 144;
        unsigned vL = vH + 9216;
        cp16(vH + fc * 16,       VhiT_ + vro + fc * 8);
        cp16(vH + (fc + 4) * 16, VhiT_ + vro + (fc + 4) * 8);
        cp16(vL + fc * 16,       VloT_ + vro + fc * 8);
        cp16(vL + (fc + 4) * 16, VloT_ + vro + (fc + 4) * 8);
    };

    fillKV(0, 0);
    cp_commit();
    if (nkt > 1) fillKV(1, 64);
    cp_commit();

    float o[8][4];
    float mrun0 = MASKV, mrun1 = MASKV;
    float lrun0 = 0.0f,  lrun1 = 0.0f;
#pragma unroll
    for (int j = 0; j < 8; j++)
#pragma unroll
        for (int e = 0; e < 4; e++) o[j][e] = 0.0f;

    for (int kt = 0; kt < nkt; kt++) {
        const int c0 = kt * 64;
        if (kt + 1 < nkt) cp_wait<1>(); else cp_wait<0>();
        __syncthreads();

        const unsigned kbase = sbase + 36864 + (kt & 1) * 18432;
        const unsigned vbase = sbase + 73728 + (kt & 1) * 18432;

        if (c0 <= wrow + 15) {
            float p[8][4];
#pragma unroll
            for (int j = 0; j < 8; j++)
#pragma unroll
                for (int e = 0; e < 4; e++) p[j][e] = 0.0f;

#pragma unroll
            for (int kc = 0; kc < 4; kc++) {
                unsigned ah[4], al[4];
                ldsm4(ah[0], ah[1], ah[2], ah[3], sbase + qoff + kc * 32);
                ldsm4(al[0], al[1], al[2], al[3], sbase + 18432 + qoff + kc * 32);
#pragma unroll
                for (int jp = 0; jp < 4; jp++) {
                    unsigned kh[4], kl[4];
                    ldsm4(kh[0], kh[1], kh[2], kh[3], kbase + boff[jp] + kc * 32);
                    ldsm4(kl[0], kl[1], kl[2], kl[3], kbase + 9216 + boff[jp] + kc * 32);
                    mma16816h(p[2 * jp],     ah, kh);
                    mma16816h(p[2 * jp],     ah, kl);
                    mma16816h(p[2 * jp],     al, kh);
                    mma16816h(p[2 * jp + 1], ah, kh + 2);
                    mma16816h(p[2 * jp + 1], ah, kl + 2);
                    mma16816h(p[2 * jp + 1], al, kh + 2);
                }
            }

            if (c0 + 63 > wrow) {
                int r0 = wrow + g, r1 = wrow + g + 8;
#pragma unroll
                for (int j = 0; j < 8; j++) {
                    int cA = c0 + j * 8 + 2 * tig;
                    if (cA     > r0) p[j][0] = MASKV;
                    if (cA + 1 > r0) p[j][1] = MASKV;
                    if (cA     > r1) p[j][2] = MASKV;
                    if (cA + 1 > r1) p[j][3] = MASKV;
                }
            }

            float mt0 = MASKV, mt1 = MASKV;
#pragma unroll
            for (int j = 0; j < 8; j++) {
                mt0 = fmaxf(mt0, fmaxf(p[j][0], p[j][1]));
                mt1 = fmaxf(mt1, fmaxf(p[j][2], p[j][3]));
            }
            mt0 = fmaxf(mt0, __shfl_xor_sync(0xffffffffu, mt0, 1));
            mt0 = fmaxf(mt0, __shfl_xor_sync(0xffffffffu, mt0, 2));
            mt1 = fmaxf(mt1, __shfl_xor_sync(0xffffffffu, mt1, 1));
            mt1 = fmaxf(mt1, __shfl_xor_sync(0xffffffffu, mt1, 2));

            float mnew0 = fmaxf(mrun0, mt0);
            float mnew1 = fmaxf(mrun1, mt1);
            float corr0, corr1;
            {
                float d0 = fmaxf(mrun0 - mnew0, -126.0f);
                float d1 = fmaxf(mrun1 - mnew1, -126.0f);
                asm("ex2.approx.f32 %0, %1;" : "=f"(corr0) : "f"(d0));
                asm("ex2.approx.f32 %0, %1;" : "=f"(corr1) : "f"(d1));
            }
            mrun0 = mnew0; mrun1 = mnew1;

            unsigned pf[8][2];
#pragma unroll
            for (int j = 0; j < 8; j++) {
                float y0 = fmaxf(p[j][0] - mnew0, YCLAMP);
                float y1 = fmaxf(p[j][1] - mnew0, YCLAMP);
                float y2 = fmaxf(p[j][2] - mnew1, YCLAMP);
                float y3 = fmaxf(p[j][3] - mnew1, YCLAMP);
                unsigned t0, t1;
                asm("cvt.rn.f16x2.f32 %0, %1, %2;" : "=r"(t0) : "f"(y1), "f"(y0));
                asm("cvt.rn.f16x2.f32 %0, %1, %2;" : "=r"(t1) : "f"(y3), "f"(y2));
                asm("ex2.approx.f16x2 %0, %0;" : "+r"(t0));
                asm("ex2.approx.f16x2 %0, %0;" : "+r"(t1));
                pf[j][0] = t0;
                pf[j][1] = t1;
                o[j][0] *= corr0; o[j][1] *= corr0;
                o[j][2] *= corr1; o[j][3] *= corr1;
            }

            float ltmp[4] = {0.0f, 0.0f, 0.0f, 0.0f};
            const unsigned ones2[2] = {0x3C003C00u, 0x3C003C00u};
#pragma unroll
            for (int kc = 0; kc < 4; kc++) {
                unsigned pa[4] = {pf[2 * kc][0], pf[2 * kc][1],
                                  pf[2 * kc + 1][0], pf[2 * kc + 1][1]};
                mma16816h(ltmp, pa, ones2);
#pragma unroll
                for (int jp = 0; jp < 4; jp++) {
                    unsigned vh[4], vl[4];
                    ldsm4(vh[0], vh[1], vh[2], vh[3], vbase + boff[jp] + kc * 32);
                    ldsm4(vl[0], vl[1], vl[2], vl[3], vbase + 9216 + boff[jp] + kc * 32);
                    mma16816h(o[2 * jp],     pa, vh);
                    mma16816h(o[2 * jp],     pa, vl);
                    mma16816h(o[2 * jp + 1], pa, vh + 2);
                    mma16816h(o[2 * jp + 1], pa, vl + 2);
                }
            }
            lrun0 = lrun0 * corr0 + ltmp[0];
            lrun1 = lrun1 * corr1 + ltmp[2];
        }

        __syncthreads();
        if (kt + 2 < nkt) {
            fillKV(kt & 1, c0 + 128);
            cp_commit();
        }
    }

    float inv0 = 1.0f / lrun0;
    float inv1 = 1.0f / lrun1;
#pragma unroll
    for (int j = 0; j < 8; j++) {
        int dh = j * 8 + 2 * tig;
        size_t r0 = ((size_t)b * SS + wrow + g) * DD + h * DH + dh;
        size_t r1 = ((size_t)b * SS + wrow + g + 8) * DD + h * DH + dh;
        unsigned h0, l0, h1, l1;
        split2h(o[j][0] * inv0, o[j][1] * inv0, h0, l0);
        split2h(o[j][2] * inv1, o[j][3] * inv1, h1, l1);
        *(unsigned*)(CtxHi + r0) = h0;
        *(unsigned*)(CtxLo + r0) = l0;
        *(unsigned*)(CtxHi + r1) = h1;
        *(unsigned*)(CtxLo + r1) = l1;
    }
}

// ---------------------------------------------------------------------------
// Launch
// ---------------------------------------------------------------------------
extern "C" void kernel_launch(void* const* d_in, const int* in_sizes, int n_in,
                              void* d_out, int out_size)
{
    const float* q  = (const float*)d_in[0];
    const float* k  = (const float*)d_in[1];
    const float* v  = (const float*)d_in[2];
    // d_in[3] = mask (causal; analytic)
    const float* wq = (const float*)d_in[4];
    const float* bq = (const float*)d_in[5];
    const float* wk = (const float*)d_in[6];
    const float* bk = (const float*)d_in[7];
    const float* wv = (const float*)d_in[8];
    const float* bv = (const float*)d_in[9];
    const float* wo = (const float*)d_in[10];
    const float* bo = (const float*)d_in[11];
    float* out = (float*)d_out;

    __half *actHi, *actLo, *wHi, *wLo;
    __half *Qhi, *Qlo, *Khi, *Klo, *Vhi, *Vlo;
    cudaGetSymbolAddress((void**)&actHi, g_ActHi);
    cudaGetSymbolAddress((void**)&actLo, g_ActLo);
    cudaGetSymbolAddress((void**)&wHi,  g_WHi);
    cudaGetSymbolAddress((void**)&wLo,  g_WLo);
    cudaGetSymbolAddress((void**)&Qhi, g_Qhi);
    cudaGetSymbolAddress((void**)&Qlo, g_Qlo);
    cudaGetSymbolAddress((void**)&Khi, g_Khi);
    cudaGetSymbolAddress((void**)&Klo, g_Klo);
    cudaGetSymbolAddress((void**)&Vhi, g_Vhi);
    cudaGetSymbolAddress((void**)&Vlo, g_Vlo);

    cudaFuncSetAttribute(flash_attn_tc, cudaFuncAttributeMaxDynamicSharedMemorySize,
                         FA_SMEM);
    cudaFuncSetAttribute(gemm_f16split<0>, cudaFuncAttributeMaxDynamicSharedMemorySize,
                         G_SMEM);
    cudaFuncSetAttribute(gemm_f16split<1>, cudaFuncAttributeMaxDynamicSharedMemorySize,
                         G_SMEM);
    cudaFuncSetAttribute(gemm_f16split<2>, cudaFuncAttributeMaxDynamicSharedMemorySize,
                         G_SMEM);

    dim3 sa(((MM * DD / 4) + 255) / 256, 3);
    dim3 sw(((DD * DD / 4) + 255) / 256, 4);
    dim3 gg(DD / GBN, MM / GBM);         // (8, 32)
    dim3 fg(SS / 128, HH, BB);           // (16, 16, 4)

    const float qscale = 0.125f * 1.44269504088896f;  // 1/sqrt(DH) * log2(e)

    split_acts<<<sa, 256>>>(q, k, v, actHi, actLo);
    split_wts<<<sw, 256>>>(wq, wk, wv, wo, wHi, wLo);
    gemm_f16split<1><<<gg, 512, G_SMEM>>>(actHi, actLo, wHi, wLo, bq, qscale,
                                          nullptr, Qhi, Qlo);
    gemm_f16split<1><<<gg, 512, G_SMEM>>>(actHi + AP, actLo + AP, wHi + WP, wLo + WP,
                                          bk, 1.0f, nullptr, Khi, Klo);
    gemm_f16split<2><<<gg, 512, G_SMEM>>>(actHi + 2 * AP, actLo + 2 * AP,
                                          wHi + 2 * WP, wLo + 2 * WP,
                                          bv, 1.0f, nullptr, Vhi, Vlo);
    flash_attn_tc<<<fg, 256, FA_SMEM>>>(Qhi, Qlo, Khi, Klo, Vhi, Vlo, actHi, actLo);
    gemm_f16split<0><<<gg, 512, G_SMEM>>>(actHi, actLo, wHi + 3 * WP, wLo + 3 * WP,
                                          bo, 1.0f, out, nullptr, nullptr);
}